// round 7
// baseline (speedup 1.0000x reference)
#include <cuda_runtime.h>
#include <cuda_fp16.h>
#include <cstdint>

#define N_HEADS 4
#define H_DIM   128
#define TOK_F   512
#define K_DIM   4096
#define BLK     32
#define STRIDE  16
#define MAXSEQ  256

#define NSTEPS  64
#define KT      64              // K halves per step
#define A_BYTES 16384           // 128 rows x 128B
#define B_BYTES 16384           // 128 rows x 128B
#define SMEM_GEMM (2 * A_BYTES + 3 * B_BYTES + 128)

// ---------------- device scratch ----------------
__device__ int    g_bases[65536];
__device__ int    g_total_out;
__device__ __half g_wT[2][(size_t)K_DIM * H_DIM];   // [mat][n*4096 + k] = w[k*128+n]

static __device__ __forceinline__ uint32_t smem_u32(const void* p) {
    uint32_t a;
    asm("{ .reg .u64 t; cvta.to.shared.u64 t, %1; cvt.u32.u64 %0, t; }" : "=r"(a) : "l"(p));
    return a;
}

#define CP_ASYNC16(dst, src) \
    asm volatile("cp.async.cg.shared.global [%0], [%1], 16;" :: "r"(dst), "l"(src) : "memory")
#define CP_COMMIT() asm volatile("cp.async.commit_group;" ::: "memory")
#define CP_WAIT1()  asm volatile("cp.async.wait_group 1;" ::: "memory")

#define LDMATRIX_X4(r0, r1, r2, r3, addr) \
    asm volatile("ldmatrix.sync.aligned.m8n8.x4.shared.b16 {%0,%1,%2,%3}, [%4];" \
                 : "=r"(r0), "=r"(r1), "=r"(r2), "=r"(r3) : "r"(addr))

// fp16-accumulate MMA
#define MMAF16(c, a0, a1, a2, a3, b0, b1) \
    asm volatile("mma.sync.aligned.m16n8k16.row.col.f16.f16.f16.f16 " \
                 "{%0,%1}, {%2,%3,%4,%5}, {%6,%7}, {%0,%1};" \
                 : "+r"((c)[0]), "+r"((c)[1]) \
                 : "r"(a0), "r"(a1), "r"(a2), "r"(a3), "r"(b0), "r"(b1))

// ---------------- kernel 1: prep = ragged metadata + W transpose/convert ----------------
__global__ void prep_kernel(const int* __restrict__ cu, int nseq,
                            const float* __restrict__ wk, const float* __restrict__ wv,
                            float* __restrict__ dout) {
    if (blockIdx.x == 1024) {
        __shared__ int s_ol[MAXSEQ];
        __shared__ int s_cu[MAXSEQ + 1];
        int t = threadIdx.y * 32 + threadIdx.x;
        if (t < nseq) {
            int n = cu[t + 1] - cu[t];
            s_ol[t] = (n >= BLK) ? (n - BLK) / STRIDE : 0;
        }
        __syncthreads();
        if (t == 0) {
            int acc = 0;
            s_cu[0] = 0;
            for (int b = 0; b < nseq; b++) { acc += s_ol[b]; s_cu[b + 1] = acc; }
            g_total_out = acc;
        }
        __syncthreads();
        int total = s_cu[nseq];
        for (int i = t; i <= nseq; i += 256)
            dout[(size_t)2 * total * 512 + i] = (float)s_cu[i];
        for (int o = t; o < total; o += 256) {
            int b = 0;
            while (s_cu[b + 1] <= o) b++;
            g_bases[o] = cu[b] + (o - s_cu[b]) * STRIDE;
        }
        return;
    }
    __shared__ float tile[32][33];
    int bx = blockIdx.x;
    int z   = bx >> 9;
    int rem = bx & 511;
    int kb  = rem & 127;
    int nb  = rem >> 7;
    const float* w = z ? wv : wk;
    __half* out = g_wT[z];
    int k0 = kb * 32, n0 = nb * 32;
    int tx = threadIdx.x, ty = threadIdx.y;   // (32, 8)
#pragma unroll
    for (int i = 0; i < 32; i += 8)
        tile[ty + i][tx] = w[(size_t)(k0 + ty + i) * H_DIM + n0 + tx];
    __syncthreads();
#pragma unroll
    for (int i = 0; i < 32; i += 8)
        out[(size_t)(n0 + ty + i) * K_DIM + k0 + tx] = __float2half_rn(tile[tx][ty + i]);
}

// ---------------- kernel 2: HMMA GEMM ----------------
// 256 thr = 8 warps in 2(M) x 4(N); warp tile 64x32; CTA tile 128x128; K-step 64.
// fp16 acc over 2-step window, fp32 flush. A double-buffer, B triple-buffer.
__global__ __launch_bounds__(256, 1)
void gemm_kernel(const float* __restrict__ kin, const float* __restrict__ vin,
                 float* __restrict__ dout) {
    extern __shared__ __align__(128) char smem[];
    const uint32_t sa = smem_u32(smem);            // A: 2 x 16KB
    const uint32_t sb = sa + 2 * A_BYTES;          // B: 3 x 16KB
    int* s_base = (int*)(smem + 2 * A_BYTES + 3 * B_BYTES);

    const int tid = threadIdx.x;
    const int wid = tid >> 5;
    const int lid = tid & 31;
    const int total_out = g_total_out;
    const int o0 = blockIdx.x * 32;               // 32 output blocks (128 rows) per CTA
    if (o0 >= total_out) return;

    const int mat = blockIdx.y;
    const float* __restrict__ x = mat ? vin : kin;
    const __half* __restrict__ wT = g_wT[mat];
    float* __restrict__ outp = dout + (size_t)mat * (size_t)total_out * 512;

    if (tid < 32) {
        int o = o0 + tid;
        if (o >= total_out) o = total_out - 1;
        s_base[tid] = g_bases[o];
    }
    __syncthreads();

    // ---- A: thread handles row m = tid>>1 (0..127), float cols q*32..+31 ----
    const int m_row = tid >> 1;
    const int q     = tid & 1;
    const float* aptr = x + (size_t)s_base[m_row >> 2] * TOK_F
                          + (size_t)(m_row & 3) * H_DIM + q * 32;
    uint32_t ast[4];
#pragma unroll
    for (int i = 0; i < 4; i++)
        ast[i] = (uint32_t)(m_row * 128 + (((q * 4 + i) ^ (m_row & 7)) * 16));

    // ---- B cp.async: thread handles n = tid>>1, chunks (tid&1)*4 + i ----
    const __half* bsrc0;
    uint32_t bdst[4];
    {
        int n = tid >> 1, c0 = (tid & 1) * 4;
        bsrc0 = wT + (size_t)n * K_DIM + c0 * 8;
#pragma unroll
        for (int i = 0; i < 4; i++)
            bdst[i] = sb + (uint32_t)(n * 128 + (((c0 + i) ^ (n & 7)) * 16));
    }

    // ---- ldmatrix addresses ----
    const int wr = wid >> 2;       // M position 0..1 (64 rows each)
    const int wc = wid & 3;        // N position 0..3 (32 cols each)
    const int g  = lid >> 3;       // tile group 0..3
    const int l7 = lid & 7;
    uint32_t lma[4][4];            // [ma][k16i]
#pragma unroll
    for (int ma = 0; ma < 4; ma++) {
        int r = wr * 64 + ma * 16 + (g & 1) * 8 + l7;
#pragma unroll
        for (int k16i = 0; k16i < 4; k16i++) {
            int c = (2 * k16i + (g >> 1)) ^ (r & 7);
            lma[ma][k16i] = sa + (uint32_t)(r * 128 + c * 16);
        }
    }
    uint32_t lmb[2][4];            // [p][k16i], p covers n-atoms 2p,2p+1
#pragma unroll
    for (int p = 0; p < 2; p++) {
        int n = wc * 32 + (2 * p + (g >> 1)) * 8 + l7;
#pragma unroll
        for (int k16i = 0; k16i < 4; k16i++) {
            int c = (2 * k16i + (g & 1)) ^ (n & 7);
            lmb[p][k16i] = sb + (uint32_t)(n * 128 + c * 16);
        }
    }

    float acc[4][4][4];            // fp32 masters [ma][na][e]
    uint32_t facc[4][4][2];        // fp16 window accumulators
#pragma unroll
    for (int ma = 0; ma < 4; ma++)
#pragma unroll
        for (int na = 0; na < 4; na++) {
#pragma unroll
            for (int e = 0; e < 4; e++) acc[ma][na][e] = 0.f;
            facc[ma][na][0] = 0u; facc[ma][na][1] = 0u;
        }

    // ---- prologue: B steps 0,1; A step 0 ----
#pragma unroll
    for (int i = 0; i < 4; i++) CP_ASYNC16(bdst[i], bsrc0 + i * 8);
    CP_COMMIT();
#pragma unroll
    for (int i = 0; i < 4; i++) CP_ASYNC16(bdst[i] + B_BYTES, bsrc0 + KT + i * 8);
    CP_COMMIT();
    {
        float4 rv[8];
#pragma unroll
        for (int i = 0; i < 8; i++) rv[i] = *(const float4*)(aptr + 4 * i);
#pragma unroll
        for (int j = 0; j < 4; j++) {
            __half2 h;
            uint4 st;
            h = __floats2half2_rn(rv[2*j].x,   rv[2*j].y);   st.x = *(uint32_t*)&h;
            h = __floats2half2_rn(rv[2*j].z,   rv[2*j].w);   st.y = *(uint32_t*)&h;
            h = __floats2half2_rn(rv[2*j+1].x, rv[2*j+1].y); st.z = *(uint32_t*)&h;
            h = __floats2half2_rn(rv[2*j+1].z, rv[2*j+1].w); st.w = *(uint32_t*)&h;
            *(uint4*)(smem + ast[j]) = st;
        }
    }

    int b3 = 0;                    // s % 3
#pragma unroll 1
    for (int s = 0; s < NSTEPS; s++) {
        CP_WAIT1();
        __syncthreads();

        // B for step s+2 into slot (s+2)%3 -- safe: everyone is past step s-1
        if (s + 2 < NSTEPS) {
            int b3n = b3 + 2; if (b3n >= 3) b3n -= 3;
            const int koff = (s + 2) * KT;
#pragma unroll
            for (int i = 0; i < 4; i++)
                CP_ASYNC16(bdst[i] + b3n * B_BYTES, bsrc0 + koff + i * 8);
        }
        CP_COMMIT();

        // prefetch A for step s+1 (8 x float4 = 128B per thread)
        float4 rv[8];
        const bool pf = (s + 1 < NSTEPS);
        if (pf) {
            const int aoff = ((s + 1) >> 1) * TOK_F + ((s + 1) & 1) * KT;
#pragma unroll
            for (int i = 0; i < 8; i++) rv[i] = *(const float4*)(aptr + aoff + 4 * i);
        }

        // compute from A slot (s&1), B slot (s%3)
        const uint32_t abuf = (uint32_t)((s & 1) * A_BYTES);
        const uint32_t bbuf = (uint32_t)(b3 * B_BYTES);
#pragma unroll
        for (int k16i = 0; k16i < 4; k16i++) {
            uint32_t b0[4], b1[4];
            LDMATRIX_X4(b0[0], b0[1], b0[2], b0[3], lmb[0][k16i] + bbuf);
            LDMATRIX_X4(b1[0], b1[1], b1[2], b1[3], lmb[1][k16i] + bbuf);
#pragma unroll
            for (int ma = 0; ma < 4; ma++) {
                uint32_t a[4];
                LDMATRIX_X4(a[0], a[1], a[2], a[3], lma[ma][k16i] + abuf);
                MMAF16(facc[ma][0], a[0], a[1], a[2], a[3], b0[0], b0[1]);
                MMAF16(facc[ma][1], a[0], a[1], a[2], a[3], b0[2], b0[3]);
                MMAF16(facc[ma][2], a[0], a[1], a[2], a[3], b1[0], b1[1]);
                MMAF16(facc[ma][3], a[0], a[1], a[2], a[3], b1[2], b1[3]);
            }
        }

        // flush fp16 window into fp32 every 2 steps
        if (s & 1) {
#pragma unroll
            for (int ma = 0; ma < 4; ma++)
#pragma unroll
                for (int na = 0; na < 4; na++) {
                    float2 f0 = __half22float2(*reinterpret_cast<__half2*>(&facc[ma][na][0]));
                    float2 f1 = __half22float2(*reinterpret_cast<__half2*>(&facc[ma][na][1]));
                    acc[ma][na][0] += f0.x; acc[ma][na][1] += f0.y;
                    acc[ma][na][2] += f1.x; acc[ma][na][3] += f1.y;
                    facc[ma][na][0] = 0u; facc[ma][na][1] = 0u;
                }
        }

        // store prefetched A into slot (s+1)&1 -- safe after syncthreads(s)
        if (pf) {
            const uint32_t nbuf = (uint32_t)(((s + 1) & 1) * A_BYTES);
#pragma unroll
            for (int j = 0; j < 4; j++) {
                __half2 h;
                uint4 st;
                h = __floats2half2_rn(rv[2*j].x,   rv[2*j].y);   st.x = *(uint32_t*)&h;
                h = __floats2half2_rn(rv[2*j].z,   rv[2*j].w);   st.y = *(uint32_t*)&h;
                h = __floats2half2_rn(rv[2*j+1].x, rv[2*j+1].y); st.z = *(uint32_t*)&h;
                h = __floats2half2_rn(rv[2*j+1].z, rv[2*j+1].w); st.w = *(uint32_t*)&h;
                *(uint4*)(smem + ast[j] + nbuf) = st;
            }
        }

        b3 += 1; if (b3 >= 3) b3 -= 3;
    }

    // ---- epilogue ----
    const int Rmax = total_out * 4;
    const int l4 = lid >> 2, lc = lid & 3;
#pragma unroll
    for (int ma = 0; ma < 4; ma++) {
        int R0 = o0 * 4 + wr * 64 + ma * 16 + l4;
#pragma unroll
        for (int na = 0; na < 4; na++) {
            int col = wc * 32 + na * 8 + lc * 2;
            if (R0 < Rmax)
                *(float2*)(outp + (size_t)R0 * 128 + col) =
                    make_float2(acc[ma][na][0], acc[ma][na][1]);
            if (R0 + 8 < Rmax)
                *(float2*)(outp + (size_t)(R0 + 8) * 128 + col) =
                    make_float2(acc[ma][na][2], acc[ma][na][3]);
        }
    }
}

// ---------------- launch ----------------
extern "C" void kernel_launch(void* const* d_in, const int* in_sizes, int n_in,
                              void* d_out, int out_size) {
    const float* k  = (const float*)d_in[0];
    const float* v  = (const float*)d_in[1];
    const float* wk = (const float*)d_in[2];
    const float* wv = (const float*)d_in[3];
    const int*   cu = (const int*)d_in[4];
    int nseq = in_sizes[4] - 1;
    int total_tokens = in_sizes[0] / (N_HEADS * H_DIM);

    prep_kernel<<<1025, dim3(32, 8)>>>(cu, nseq, wk, wv, (float*)d_out);

    int max_out = total_tokens / STRIDE;
    int ntiles = (max_out + 31) / 32;
    cudaFuncSetAttribute(gemm_kernel, cudaFuncAttributeMaxDynamicSharedMemorySize, SMEM_GEMM);
    gemm_kernel<<<dim3(ntiles, 2), 256, SMEM_GEMM>>>(k, v, (float*)d_out);
}

// round 9
// speedup vs baseline: 1.4835x; 1.4835x over previous
#include <cuda_runtime.h>
#include <cuda_fp16.h>
#include <cstdint>

#define N_HEADS 4
#define H_DIM   128
#define TOK_F   512
#define K_DIM   4096
#define BLK     32
#define STRIDE  16
#define MAXSEQ  256

#define NSTEPS  64
#define KT      64              // K halves per step
#define A_BYTES 8192            // 64 rows x 128B
#define B_BYTES 16384           // 128 rows x 128B
#define SMEM_GEMM (2 * A_BYTES + 4 * B_BYTES + 128)

// ---------------- device scratch ----------------
__device__ int    g_bases[65536];
__device__ int    g_total_out;
__device__ __half g_wT[2][(size_t)K_DIM * H_DIM];   // [mat][n*4096 + k] = w[k*128+n]

static __device__ __forceinline__ uint32_t smem_u32(const void* p) {
    uint32_t a;
    asm("{ .reg .u64 t; cvta.to.shared.u64 t, %1; cvt.u32.u64 %0, t; }" : "=r"(a) : "l"(p));
    return a;
}

#define CP_ASYNC16(dst, src) \
    asm volatile("cp.async.cg.shared.global [%0], [%1], 16;" :: "r"(dst), "l"(src) : "memory")
#define CP_COMMIT()  asm volatile("cp.async.commit_group;" ::: "memory")
#define CP_WAITALL() asm volatile("cp.async.wait_all;" ::: "memory")

#define BAR_HALF(id) \
    asm volatile("bar.sync %0, 128;" :: "r"(id) : "memory")

#define LDMATRIX_X4(r0, r1, r2, r3, addr) \
    asm volatile("ldmatrix.sync.aligned.m8n8.x4.shared.b16 {%0,%1,%2,%3}, [%4];" \
                 : "=r"(r0), "=r"(r1), "=r"(r2), "=r"(r3) : "r"(addr))

// fp16-accumulate MMA: D,C packed half2 x2
#define MMAF16(c, a0, a1, a2, a3, b0, b1) \
    asm volatile("mma.sync.aligned.m16n8k16.row.col.f16.f16.f16.f16 " \
                 "{%0,%1}, {%2,%3,%4,%5}, {%6,%7}, {%0,%1};" \
                 : "+r"((c)[0]), "+r"((c)[1]) \
                 : "r"(a0), "r"(a1), "r"(a2), "r"(a3), "r"(b0), "r"(b1))

// ---------------- kernel 1: prep = ragged metadata + W transpose/convert ----------------
__global__ void prep_kernel(const int* __restrict__ cu, int nseq,
                            const float* __restrict__ wk, const float* __restrict__ wv,
                            float* __restrict__ dout) {
    if (blockIdx.x == 1024) {
        __shared__ int s_ol[MAXSEQ];
        __shared__ int s_cu[MAXSEQ + 1];
        int t = threadIdx.y * 32 + threadIdx.x;
        if (t < nseq) {
            int n = cu[t + 1] - cu[t];
            s_ol[t] = (n >= BLK) ? (n - BLK) / STRIDE : 0;
        }
        __syncthreads();
        if (t == 0) {
            int acc = 0;
            s_cu[0] = 0;
            for (int b = 0; b < nseq; b++) { acc += s_ol[b]; s_cu[b + 1] = acc; }
            g_total_out = acc;
        }
        __syncthreads();
        int total = s_cu[nseq];
        for (int i = t; i <= nseq; i += 256)
            dout[(size_t)2 * total * 512 + i] = (float)s_cu[i];
        for (int o = t; o < total; o += 256) {
            int b = 0;
            while (s_cu[b + 1] <= o) b++;
            g_bases[o] = cu[b] + (o - s_cu[b]) * STRIDE;
        }
        return;
    }
    __shared__ float tile[32][33];
    int bx = blockIdx.x;
    int z   = bx >> 9;
    int rem = bx & 511;
    int kb  = rem & 127;
    int nb  = rem >> 7;
    const float* w = z ? wv : wk;
    __half* out = g_wT[z];
    int k0 = kb * 32, n0 = nb * 32;
    int tx = threadIdx.x, ty = threadIdx.y;   // (32, 8)
#pragma unroll
    for (int i = 0; i < 32; i += 8)
        tile[ty + i][tx] = w[(size_t)(k0 + ty + i) * H_DIM + n0 + tx];
    __syncthreads();
#pragma unroll
    for (int i = 0; i < 32; i += 8)
        out[(size_t)(n0 + ty + i) * K_DIM + k0 + tx] = __float2half_rn(tile[tx][ty + i]);
}

// store 4 float4 (32 fp32) as 2 swizzled uint4 rows of fp16
static __device__ __forceinline__ void cvt_store_A(char* smem, uint32_t ast0, uint32_t ast1,
                                                   const float4* rv) {
    __half2 h;
    uint4 s0, s1;
    h = __floats2half2_rn(rv[0].x, rv[0].y); s0.x = *(uint32_t*)&h;
    h = __floats2half2_rn(rv[0].z, rv[0].w); s0.y = *(uint32_t*)&h;
    h = __floats2half2_rn(rv[1].x, rv[1].y); s0.z = *(uint32_t*)&h;
    h = __floats2half2_rn(rv[1].z, rv[1].w); s0.w = *(uint32_t*)&h;
    h = __floats2half2_rn(rv[2].x, rv[2].y); s1.x = *(uint32_t*)&h;
    h = __floats2half2_rn(rv[2].z, rv[2].w); s1.y = *(uint32_t*)&h;
    h = __floats2half2_rn(rv[3].x, rv[3].y); s1.z = *(uint32_t*)&h;
    h = __floats2half2_rn(rv[3].z, rv[3].w); s1.w = *(uint32_t*)&h;
    *(uint4*)(smem + ast0) = s0;
    *(uint4*)(smem + ast1) = s1;
}

// ---------------- kernel 2: HMMA GEMM ----------------
// 256 thr = 8 warps in 2(M) x 4(N); warp tile 32x32; CTA tile 64x128; K-step 64.
// 2 CTAs/SM. One full __syncthreads per 2 steps (B quad-buffered, wait_all
// before barrier -> CTA-wide cp.async visibility for BOTH B tiles). A double-
// buffered with per-half named barriers (writer half == reader half).
__global__ __launch_bounds__(256, 2)
void gemm_kernel(const float* __restrict__ kin, const float* __restrict__ vin,
                 float* __restrict__ dout) {
    extern __shared__ __align__(128) char smem[];
    const uint32_t sa = smem_u32(smem);            // A: 2 x 8KB
    const uint32_t sb = sa + 2 * A_BYTES;          // B: 4 x 16KB
    int* s_base = (int*)(smem + 2 * A_BYTES + 4 * B_BYTES);

    const int tid = threadIdx.x;
    const int wid = tid >> 5;
    const int lid = tid & 31;
    const int total_out = g_total_out;
    const int o0 = blockIdx.x * 16;               // 16 output blocks (64 rows) per CTA
    if (o0 >= total_out) return;

    const int mat = blockIdx.y;
    const float* __restrict__ x = mat ? vin : kin;
    const __half* __restrict__ wT = g_wT[mat];
    float* __restrict__ outp = dout + (size_t)mat * (size_t)total_out * 512;

    if (tid < 16) {
        int o = o0 + tid;
        if (o >= total_out) o = total_out - 1;
        s_base[tid] = g_bases[o];
    }
    __syncthreads();

    // ---- A writer: half h = tid>>7 owns rows h*32..+31 (matches reader half wr) ----
    const int ht    = tid & 127;
    const int m_row = (tid >> 7) * 32 + (ht >> 2);
    const int q     = tid & 3;
    const float* aptr = x + (size_t)s_base[m_row >> 2] * TOK_F
                          + (size_t)(m_row & 3) * H_DIM + q * 16;
    const uint32_t ast0 = (uint32_t)(m_row * 128 + (((2 * q)     ^ (m_row & 7)) * 16));
    const uint32_t ast1 = (uint32_t)(m_row * 128 + (((2 * q + 1) ^ (m_row & 7)) * 16));

    // ---- B cp.async: thread handles n = tid>>1, chunks (tid&1)*4 + i ----
    const __half* bsrc0;
    uint32_t bdst[4];
    {
        int n = tid >> 1, c0 = (tid & 1) * 4;
        bsrc0 = wT + (size_t)n * K_DIM + c0 * 8;
#pragma unroll
        for (int i = 0; i < 4; i++)
            bdst[i] = sb + (uint32_t)(n * 128 + (((c0 + i) ^ (n & 7)) * 16));
    }

    // ---- ldmatrix addresses ----
    const int wr = wid >> 2;       // M position 0..1
    const int wc = wid & 3;        // N position 0..3
    const int g  = lid >> 3;       // tile group 0..3
    const int l7 = lid & 7;
    uint32_t lma[2][4];
#pragma unroll
    for (int ma = 0; ma < 2; ma++) {
        int r = wr * 32 + ma * 16 + (g & 1) * 8 + l7;
#pragma unroll
        for (int k16i = 0; k16i < 4; k16i++) {
            int c = (2 * k16i + (g >> 1)) ^ (r & 7);
            lma[ma][k16i] = sa + (uint32_t)(r * 128 + c * 16);
        }
    }
    uint32_t lmb[2][4];
#pragma unroll
    for (int p = 0; p < 2; p++) {
        int n = wc * 32 + (2 * p + (g >> 1)) * 8 + l7;
#pragma unroll
        for (int k16i = 0; k16i < 4; k16i++) {
            int c = (2 * k16i + (g & 1)) ^ (n & 7);
            lmb[p][k16i] = sb + (uint32_t)(n * 128 + c * 16);
        }
    }

    float acc[2][4][4];          // fp32 master accumulators
    uint32_t facc[2][4][2];      // fp16 window accumulators
#pragma unroll
    for (int ma = 0; ma < 2; ma++)
#pragma unroll
        for (int na = 0; na < 4; na++) {
#pragma unroll
            for (int e = 0; e < 4; e++) acc[ma][na][e] = 0.f;
            facc[ma][na][0] = 0u; facc[ma][na][1] = 0u;
        }

    // ---- prologue: B steps 0,1; A step 0 -> slot 0 ----
#pragma unroll
    for (int i = 0; i < 4; i++) CP_ASYNC16(bdst[i], bsrc0 + i * 8);
    CP_COMMIT();
#pragma unroll
    for (int i = 0; i < 4; i++) CP_ASYNC16(bdst[i] + B_BYTES, bsrc0 + KT + i * 8);
    CP_COMMIT();
    {
        float4 rv[4];
#pragma unroll
        for (int i = 0; i < 4; i++) rv[i] = *(const float4*)(aptr + 4 * i);
        cvt_store_A(smem, ast0, ast1, rv);
    }

#pragma unroll 1
    for (int s = 0; s < NSTEPS; s += 2) {
        // retire ALL outstanding B groups (for steps s, s+1), then CTA-wide publish.
        CP_WAITALL();
        __syncthreads();

        // issue B for steps s+2, s+3 into slots (s+2)&3, (s+3)&3.
        // safe: slot(s+2)&3 readers were step s-2, slot(s+3)&3 readers step s-1,
        // both done at the barrier above.
        if (s + 2 < NSTEPS) {
            const int koff = (s + 2) * KT;
#pragma unroll
            for (int i = 0; i < 4; i++)
                CP_ASYNC16(bdst[i] + ((s + 2) & 3) * B_BYTES, bsrc0 + koff + i * 8);
            CP_COMMIT();
        }
        if (s + 3 < NSTEPS) {
            const int koff = (s + 3) * KT;
#pragma unroll
            for (int i = 0; i < 4; i++)
                CP_ASYNC16(bdst[i] + ((s + 3) & 3) * B_BYTES, bsrc0 + koff + i * 8);
            CP_COMMIT();
        }

        // ======== step s (even): A slot 0, B slot s&3 ========
        float4 rv[4];
        {   // prefetch A(s+1)
            const int aoff = ((s + 1) >> 1) * TOK_F + ((s + 1) & 1) * KT;
#pragma unroll
            for (int i = 0; i < 4; i++) rv[i] = *(const float4*)(aptr + aoff + 4 * i);
        }
        {
            const uint32_t bbuf = (uint32_t)((s & 3) * B_BYTES);
#pragma unroll
            for (int k16i = 0; k16i < 4; k16i++) {
                uint32_t a0[4], a1[4], b0[4], b1[4];
                LDMATRIX_X4(a0[0], a0[1], a0[2], a0[3], lma[0][k16i]);
                LDMATRIX_X4(a1[0], a1[1], a1[2], a1[3], lma[1][k16i]);
                LDMATRIX_X4(b0[0], b0[1], b0[2], b0[3], lmb[0][k16i] + bbuf);
                LDMATRIX_X4(b1[0], b1[1], b1[2], b1[3], lmb[1][k16i] + bbuf);
                MMAF16(facc[0][0], a0[0], a0[1], a0[2], a0[3], b0[0], b0[1]);
                MMAF16(facc[0][1], a0[0], a0[1], a0[2], a0[3], b0[2], b0[3]);
                MMAF16(facc[0][2], a0[0], a0[1], a0[2], a0[3], b1[0], b1[1]);
                MMAF16(facc[0][3], a0[0], a0[1], a0[2], a0[3], b1[2], b1[3]);
                MMAF16(facc[1][0], a1[0], a1[1], a1[2], a1[3], b0[0], b0[1]);
                MMAF16(facc[1][1], a1[0], a1[1], a1[2], a1[3], b0[2], b0[3]);
                MMAF16(facc[1][2], a1[0], a1[1], a1[2], a1[3], b1[0], b1[1]);
                MMAF16(facc[1][3], a1[0], a1[1], a1[2], a1[3], b1[2], b1[3]);
            }
        }
        // store A(s+1) -> slot 1 (own half finished its slot-1 reads at step s-1,
        // which is gated by the __syncthreads above)
        cvt_store_A(smem + A_BYTES, ast0, ast1, rv);
        BAR_HALF(1 + wr);   // publish A slot 1 within this half

        // ======== step s+1 (odd): A slot 1, B slot (s+1)&3 ========
        const bool pf2 = (s + 2 < NSTEPS);
        if (pf2) {
            const int aoff = ((s + 2) >> 1) * TOK_F + ((s + 2) & 1) * KT;
#pragma unroll
            for (int i = 0; i < 4; i++) rv[i] = *(const float4*)(aptr + aoff + 4 * i);
        }
        {
            const uint32_t bbuf = (uint32_t)(((s + 1) & 3) * B_BYTES);
#pragma unroll
            for (int k16i = 0; k16i < 4; k16i++) {
                uint32_t a0[4], a1[4], b0[4], b1[4];
                LDMATRIX_X4(a0[0], a0[1], a0[2], a0[3], lma[0][k16i] + A_BYTES);
                LDMATRIX_X4(a1[0], a1[1], a1[2], a1[3], lma[1][k16i] + A_BYTES);
                LDMATRIX_X4(b0[0], b0[1], b0[2], b0[3], lmb[0][k16i] + bbuf);
                LDMATRIX_X4(b1[0], b1[1], b1[2], b1[3], lmb[1][k16i] + bbuf);
                MMAF16(facc[0][0], a0[0], a0[1], a0[2], a0[3], b0[0], b0[1]);
                MMAF16(facc[0][1], a0[0], a0[1], a0[2], a0[3], b0[2], b0[3]);
                MMAF16(facc[0][2], a0[0], a0[1], a0[2], a0[3], b1[0], b1[1]);
                MMAF16(facc[0][3], a0[0], a0[1], a0[2], a0[3], b1[2], b1[3]);
                MMAF16(facc[1][0], a1[0], a1[1], a1[2], a1[3], b0[0], b0[1]);
                MMAF16(facc[1][1], a1[0], a1[1], a1[2], a1[3], b0[2], b0[3]);
                MMAF16(facc[1][2], a1[0], a1[1], a1[2], a1[3], b1[0], b1[1]);
                MMAF16(facc[1][3], a1[0], a1[1], a1[2], a1[3], b1[2], b1[3]);
            }
        }
        // flush fp16 window into fp32 (window = steps s, s+1)
#pragma unroll
        for (int ma = 0; ma < 2; ma++)
#pragma unroll
            for (int na = 0; na < 4; na++) {
                float2 f0 = __half22float2(*reinterpret_cast<__half2*>(&facc[ma][na][0]));
                float2 f1 = __half22float2(*reinterpret_cast<__half2*>(&facc[ma][na][1]));
                acc[ma][na][0] += f0.x; acc[ma][na][1] += f0.y;
                acc[ma][na][2] += f1.x; acc[ma][na][3] += f1.y;
                facc[ma][na][0] = 0u; facc[ma][na][1] = 0u;
            }
        // store A(s+2) -> slot 0 (own half passed BAR_HALF after its slot-0 reads
        // at step s; next readers gated by next block's __syncthreads)
        if (pf2) cvt_store_A(smem, ast0, ast1, rv);
    }

    // ---- epilogue ----
    const int Rmax = total_out * 4;
    const int l4 = lid >> 2, lc = lid & 3;
#pragma unroll
    for (int ma = 0; ma < 2; ma++) {
        int R0 = o0 * 4 + wr * 32 + ma * 16 + l4;
#pragma unroll
        for (int na = 0; na < 4; na++) {
            int col = wc * 32 + na * 8 + lc * 2;
            if (R0 < Rmax)
                *(float2*)(outp + (size_t)R0 * 128 + col) =
                    make_float2(acc[ma][na][0], acc[ma][na][1]);
            if (R0 + 8 < Rmax)
                *(float2*)(outp + (size_t)(R0 + 8) * 128 + col) =
                    make_float2(acc[ma][na][2], acc[ma][na][3]);
        }
    }
}

// ---------------- launch ----------------
extern "C" void kernel_launch(void* const* d_in, const int* in_sizes, int n_in,
                              void* d_out, int out_size) {
    const float* k  = (const float*)d_in[0];
    const float* v  = (const float*)d_in[1];
    const float* wk = (const float*)d_in[2];
    const float* wv = (const float*)d_in[3];
    const int*   cu = (const int*)d_in[4];
    int nseq = in_sizes[4] - 1;
    int total_tokens = in_sizes[0] / (N_HEADS * H_DIM);

    prep_kernel<<<1025, dim3(32, 8)>>>(cu, nseq, wk, wv, (float*)d_out);

    int max_out = total_tokens / STRIDE;
    int ntiles = (max_out + 15) / 16;
    cudaFuncSetAttribute(gemm_kernel, cudaFuncAttributeMaxDynamicSharedMemorySize, SMEM_GEMM);
    gemm_kernel<<<dim3(ntiles, 2), 256, SMEM_GEMM>>>(k, v, (float*)d_out);
}